// round 1
// baseline (speedup 1.0000x reference)
#include <cuda_runtime.h>
#include <cuda_bf16.h>
#include <stdint.h>

// Problem constants (fixed by the dataset)
#define NNODES 100000
#define NEDGES 1600000
#define FDIM   128      // in_dim == hid == 128
#define LAT    64

// ---------------- scratch (static __device__ globals: allowed) -------------
__device__ float g_t[(size_t)NNODES * FDIM];    // t = x @ W1            (51.2 MB)
__device__ float g_agg[(size_t)NNODES * FDIM];  // scatter accumulator   (51.2 MB)
__device__ float g_deg[NNODES];
__device__ float g_dinv[NNODES];
__device__ float g_c[NNODES];                   // column sums of Anorm
__device__ float g_norm[NEDGES];                // per-edge norm
__device__ float g_v[FDIM];                     // v = sum_i c_i * h1[i]

// ---------------- helpers --------------------------------------------------
__device__ __forceinline__ void red_add_v4(float* p, float4 m) {
    asm volatile("red.global.add.v4.f32 [%0], {%1,%2,%3,%4};"
                 :: "l"(p), "f"(m.x), "f"(m.y), "f"(m.z), "f"(m.w) : "memory");
}

// ---------------- kernels --------------------------------------------------

// zero agg, zero v, deg = 1 (self loop weight)
__global__ void k_init(int n) {
    long long i = (long long)blockIdx.x * blockDim.x + threadIdx.x;
    long long tot4 = (long long)n * (FDIM / 4);
    if (i < tot4) ((float4*)g_agg)[i] = make_float4(0.f, 0.f, 0.f, 0.f);
    if (i < n)    g_deg[i] = 1.0f;
    if (i < FDIM / 4) ((float4*)g_v)[i] = make_float4(0.f, 0.f, 0.f, 0.f);
}

// deg[dst] += w
__global__ void k_deg(const int* __restrict__ dst, const float* __restrict__ w, int e) {
    int i = blockIdx.x * blockDim.x + threadIdx.x;
    if (i < e) atomicAdd(&g_deg[dst[i]], w[i]);
}

// dinv = rsqrt(deg); c = dinv^2 (self-loop contribution)
__global__ void k_dinv(int n) {
    int i = blockIdx.x * blockDim.x + threadIdx.x;
    if (i < n) {
        float di = rsqrtf(g_deg[i]);
        g_dinv[i] = di;
        g_c[i] = di * di;
    }
}

// norm[e] = dinv[s]*w*dinv[d]; c[s] += norm[e]
__global__ void k_norm(const int* __restrict__ src, const int* __restrict__ dst,
                       const float* __restrict__ w, int e) {
    int i = blockIdx.x * blockDim.x + threadIdx.x;
    if (i < e) {
        int s = src[i], d = dst[i];
        float nm = g_dinv[s] * w[i] * g_dinv[d];
        g_norm[i] = nm;
        atomicAdd(&g_c[s], nm);
    }
}

// t = x @ W1     (n x 128) = (n x 128)(128 x 128), fp32 tiled
#define BM 64
#define BK 32
__global__ __launch_bounds__(256) void k_gemm(const float* __restrict__ x,
                                              const float* __restrict__ W,
                                              int n) {
    __shared__ float As[BK][BM];     // x tile, transposed
    __shared__ float Bs[BK][FDIM];   // W tile
    const int br  = blockIdx.x * BM;
    const int tid = threadIdx.x;
    const int ty = tid >> 4;         // 0..15 -> rows ty*4..ty*4+3
    const int tx = tid & 15;         // 0..15 -> cols tx*8..tx*8+7
    float acc[4][8];
#pragma unroll
    for (int r = 0; r < 4; r++)
#pragma unroll
        for (int c = 0; c < 8; c++) acc[r][c] = 0.f;

    for (int k0 = 0; k0 < FDIM; k0 += BK) {
        // load x tile: 64 rows x 32 k = 512 float4, 2 per thread
#pragma unroll
        for (int i = 0; i < 2; i++) {
            int li = tid * 2 + i;
            int r = li >> 3, kq = li & 7;
            int gr = br + r; if (gr >= n) gr = n - 1;
            float4 xv = __ldg((const float4*)(x + (size_t)gr * FDIM + k0) + kq);
            As[kq * 4 + 0][r] = xv.x;
            As[kq * 4 + 1][r] = xv.y;
            As[kq * 4 + 2][r] = xv.z;
            As[kq * 4 + 3][r] = xv.w;
        }
        // load W tile: 32 x 128 = 1024 float4, 4 per thread
#pragma unroll
        for (int i = 0; i < 4; i++) {
            int li = tid + i * 256;
            int k = li >> 5, cq = li & 31;
            float4 wv = __ldg((const float4*)(W + (size_t)(k0 + k) * FDIM) + cq);
            *(float4*)&Bs[k][cq * 4] = wv;
        }
        __syncthreads();
#pragma unroll 8
        for (int k = 0; k < BK; k++) {
            float4 av  = *(const float4*)&As[k][ty * 4];
            float4 bv0 = *(const float4*)&Bs[k][tx * 8];
            float4 bv1 = *(const float4*)&Bs[k][tx * 8 + 4];
            float a[4] = {av.x, av.y, av.z, av.w};
            float b[8] = {bv0.x, bv0.y, bv0.z, bv0.w, bv1.x, bv1.y, bv1.z, bv1.w};
#pragma unroll
            for (int r = 0; r < 4; r++)
#pragma unroll
                for (int c = 0; c < 8; c++) acc[r][c] = fmaf(a[r], b[c], acc[r][c]);
        }
        __syncthreads();
    }
#pragma unroll
    for (int r = 0; r < 4; r++) {
        int gr = br + ty * 4 + r;
        if (gr < n) {
            float4 o0 = make_float4(acc[r][0], acc[r][1], acc[r][2], acc[r][3]);
            float4 o1 = make_float4(acc[r][4], acc[r][5], acc[r][6], acc[r][7]);
            *(float4*)(g_t + (size_t)gr * FDIM + tx * 8)     = o0;
            *(float4*)(g_t + (size_t)gr * FDIM + tx * 8 + 4) = o1;
        }
    }
}

// edge scatter: agg[d] += norm[e] * t[s]   (one warp per edge, float4 lanes)
__global__ __launch_bounds__(256) void k_scatter(const int* __restrict__ src,
                                                 const int* __restrict__ dst,
                                                 long long total) {
    long long gid = (long long)blockIdx.x * blockDim.x + threadIdx.x;
    if (gid >= total) return;
    int e = (int)(gid >> 5);
    int l = (int)(gid & 31);
    int s = __ldg(src + e);
    int d = __ldg(dst + e);
    float nm = __ldg(g_norm + e);
    float4 tv = __ldg((const float4*)g_t + (size_t)s * 32 + l);
    float4 m = make_float4(nm * tv.x, nm * tv.y, nm * tv.z, nm * tv.w);
    red_add_v4(g_agg + ((size_t)d << 7) + (l << 2), m);
}

// finalize: h1[i] = relu(agg[i] + dinv_i^2 * t[i] + b1); v += c_i * h1[i]
__global__ __launch_bounds__(256) void k_finalize(const float* __restrict__ b1, int n) {
    const int lane = threadIdx.x & 31;
    const int wid  = threadIdx.x >> 5;
    const int gw   = blockIdx.x * 8 + wid;
    const int nw   = gridDim.x * 8;
    float4 bv = __ldg((const float4*)b1 + lane);
    float4 vacc = make_float4(0.f, 0.f, 0.f, 0.f);
    for (int i = gw; i < n; i += nw) {
        float di = g_dinv[i];
        float self = di * di;
        float ci = g_c[i];
        float4 a  = ((const float4*)g_agg)[(size_t)i * 32 + lane];
        float4 tv = __ldg((const float4*)g_t + (size_t)i * 32 + lane);
        float4 h;
        h.x = fmaxf(a.x + self * tv.x + bv.x, 0.f);
        h.y = fmaxf(a.y + self * tv.y + bv.y, 0.f);
        h.z = fmaxf(a.z + self * tv.z + bv.z, 0.f);
        h.w = fmaxf(a.w + self * tv.w + bv.w, 0.f);
        vacc.x = fmaf(ci, h.x, vacc.x);
        vacc.y = fmaf(ci, h.y, vacc.y);
        vacc.z = fmaf(ci, h.z, vacc.z);
        vacc.w = fmaf(ci, h.w, vacc.w);
    }
    __shared__ float sv[FDIM];
    if (threadIdx.x < FDIM) sv[threadIdx.x] = 0.f;
    __syncthreads();
    atomicAdd(&sv[lane * 4 + 0], vacc.x);
    atomicAdd(&sv[lane * 4 + 1], vacc.y);
    atomicAdd(&sv[lane * 4 + 2], vacc.z);
    atomicAdd(&sv[lane * 4 + 3], vacc.w);
    __syncthreads();
    if (threadIdx.x < 32) {
        float4 p = *(const float4*)&sv[threadIdx.x * 4];
        red_add_v4(g_v + threadIdx.x * 4, p);
    }
}

// head: g = (1/N) v@W2 + b2;  mu = g@Wmu + bmu;  lv = g@Wlv + blv
__global__ void k_head(const float* __restrict__ W2, const float* __restrict__ b2,
                       const float* __restrict__ Wmu, const float* __restrict__ bmu,
                       const float* __restrict__ Wlv, const float* __restrict__ blv,
                       float* __restrict__ out, float invn) {
    __shared__ float vs[FDIM];
    __shared__ float gs[FDIM];
    int j = threadIdx.x;  // 128 threads
    vs[j] = g_v[j];
    __syncthreads();
    float s = 0.f;
#pragma unroll 8
    for (int k = 0; k < FDIM; k++) s = fmaf(vs[k], W2[(size_t)k * FDIM + j], s);
    gs[j] = s * invn + b2[j];
    __syncthreads();
    if (j < LAT) {
        float m = bmu[j];
#pragma unroll 8
        for (int k = 0; k < FDIM; k++) m = fmaf(gs[k], Wmu[(size_t)k * LAT + j], m);
        out[j] = m;
    } else {
        int l = j - LAT;
        float m = blv[l];
#pragma unroll 8
        for (int k = 0; k < FDIM; k++) m = fmaf(gs[k], Wlv[(size_t)k * LAT + l], m);
        out[LAT + l] = m;
    }
}

// ---------------- launch ----------------------------------------------------
extern "C" void kernel_launch(void* const* d_in, const int* in_sizes, int n_in,
                              void* d_out, int out_size) {
    const float* x   = (const float*)d_in[0];
    const int*   ei  = (const int*)d_in[1];   // [2, E]
    const float* w   = (const float*)d_in[2];
    const float* W1  = (const float*)d_in[3];
    const float* b1  = (const float*)d_in[4];
    const float* W2  = (const float*)d_in[5];
    const float* b2  = (const float*)d_in[6];
    const float* Wmu = (const float*)d_in[7];
    const float* bmu = (const float*)d_in[8];
    const float* Wlv = (const float*)d_in[9];
    const float* blv = (const float*)d_in[10];
    float* out = (float*)d_out;

    const int n = in_sizes[0] / FDIM;   // 100000
    const int e = in_sizes[2];          // 1600000
    const int* src = ei;
    const int* dst = ei + e;

    // init: zero agg (n*32 float4), deg=1, v=0
    {
        long long tot = (long long)n * (FDIM / 4);
        int blocks = (int)((tot + 255) / 256);
        k_init<<<blocks, 256>>>(n);
    }
    k_deg<<<(e + 255) / 256, 256>>>(dst, w, e);
    k_dinv<<<(n + 255) / 256, 256>>>(n);
    k_norm<<<(e + 255) / 256, 256>>>(src, dst, w, e);
    k_gemm<<<(n + BM - 1) / BM, 256>>>(x, W1, n);
    {
        long long total = (long long)e * 32;
        int blocks = (int)((total + 255) / 256);
        k_scatter<<<blocks, 256>>>(src, dst, total);
    }
    k_finalize<<<1024, 256>>>(b1, n);
    k_head<<<1, FDIM>>>(W2, b2, Wmu, bmu, Wlv, blv, out, 1.0f / (float)n);
}

// round 2
// speedup vs baseline: 1.3539x; 1.3539x over previous
#include <cuda_runtime.h>
#include <cuda_bf16.h>
#include <stdint.h>

#define NNODES 100000
#define NEDGES 1600000
#define FDIM   128
#define LAT    64
#define SCAN_ELEMS 1024
#define NBLK_SCAN ((NNODES + SCAN_ELEMS - 1) / SCAN_ELEMS)   // 98

// ---------------- scratch ----------------------------------------------------
__device__ float g_t[(size_t)NNODES * FDIM];    // t = x @ W1  (51.2 MB)
__device__ float g_deg[NNODES];
__device__ float g_dinv[NNODES];
__device__ float g_c[NNODES];                   // column sums of Anorm
__device__ int   g_cnt[NNODES];                 // in-degree counts
__device__ int   g_rowptr[NNODES];              // CSR row starts (by dst)
__device__ int   g_fill[NNODES];                // fill cursors
__device__ int   g_bsum[NBLK_SCAN + 32];        // scan partials
__device__ int2  g_csr[NEDGES];                 // packed {src, norm-as-bits}
__device__ float g_v[FDIM];                     // v = sum_i c_i * h1[i]

__device__ __forceinline__ void red_add_v4(float* p, float4 m) {
    asm volatile("red.global.add.v4.f32 [%0], {%1,%2,%3,%4};"
                 :: "l"(p), "f"(m.x), "f"(m.y), "f"(m.z), "f"(m.w) : "memory");
}

// ---------------- kernels -----------------------------------------------------

__global__ void k_init(int n) {
    int i = blockIdx.x * blockDim.x + threadIdx.x;
    if (i < n) { g_cnt[i] = 0; g_fill[i] = 0; g_deg[i] = 1.0f; }
    if (i < FDIM) g_v[i] = 0.f;
}

// deg[dst] += w ; cnt[dst]++
__global__ void k_hist(const int* __restrict__ dst, const float* __restrict__ w, int e) {
    int i = blockIdx.x * blockDim.x + threadIdx.x;
    if (i < e) {
        int d = dst[i];
        atomicAdd(&g_deg[d], w[i]);
        atomicAdd(&g_cnt[d], 1);
    }
}

__global__ void k_dinv(int n) {
    int i = blockIdx.x * blockDim.x + threadIdx.x;
    if (i < n) {
        float di = rsqrtf(g_deg[i]);
        g_dinv[i] = di;
        g_c[i] = di * di;       // self-loop column contribution
    }
}

// ---- exclusive scan of g_cnt -> g_rowptr (3 small kernels) ----
__global__ void k_scan1(int n) {
    __shared__ int warp_sums[8];
    int tid = threadIdx.x;                 // 256 threads, 4 elems each
    int idx = blockIdx.x * SCAN_ELEMS + tid * 4;
    int4 v = make_int4(0, 0, 0, 0);
    if (idx + 3 < n) v = *(const int4*)(g_cnt + idx);
    else {
        if (idx + 0 < n) v.x = g_cnt[idx + 0];
        if (idx + 1 < n) v.y = g_cnt[idx + 1];
        if (idx + 2 < n) v.z = g_cnt[idx + 2];
        if (idx + 3 < n) v.w = g_cnt[idx + 3];
    }
    int t = v.x + v.y + v.z + v.w;
    int lane = tid & 31, wid = tid >> 5;
    int s = t;
#pragma unroll
    for (int o = 1; o < 32; o <<= 1) { int u = __shfl_up_sync(~0u, s, o); if (lane >= o) s += u; }
    if (lane == 31) warp_sums[wid] = s;
    __syncthreads();
    if (wid == 0) {
        int ws = (lane < 8) ? warp_sums[lane] : 0;
#pragma unroll
        for (int o = 1; o < 8; o <<= 1) { int u = __shfl_up_sync(~0u, ws, o); if (lane >= o) ws += u; }
        if (lane < 8) warp_sums[lane] = ws;
    }
    __syncthreads();
    int excl = s - t + (wid > 0 ? warp_sums[wid - 1] : 0);
    int o0 = excl, o1 = excl + v.x, o2 = o1 + v.y, o3 = o2 + v.z;
    if (idx + 0 < n) g_rowptr[idx + 0] = o0;
    if (idx + 1 < n) g_rowptr[idx + 1] = o1;
    if (idx + 2 < n) g_rowptr[idx + 2] = o2;
    if (idx + 3 < n) g_rowptr[idx + 3] = o3;
    if (tid == 255) g_bsum[blockIdx.x] = excl + t;
}

__global__ void k_scan2(int nb) {
    int tid = threadIdx.x;                 // 128 threads
    int v = (tid < nb) ? g_bsum[tid] : 0;
    int lane = tid & 31, wid = tid >> 5;
    int s = v;
#pragma unroll
    for (int o = 1; o < 32; o <<= 1) { int u = __shfl_up_sync(~0u, s, o); if (lane >= o) s += u; }
    __shared__ int ws[4];
    if (lane == 31) ws[wid] = s;
    __syncthreads();
    int add = 0;
    for (int k = 0; k < wid; k++) add += ws[k];
    if (tid < nb) g_bsum[tid] = s + add - v;     // exclusive
}

__global__ void k_scan3(int n) {
    int i = blockIdx.x * blockDim.x + threadIdx.x;
    if (i < n) g_rowptr[i] += g_bsum[i >> 10];
}

// CSR fill: place {src, norm} at dst-grouped position; accumulate c[src]
__global__ void k_fill(const int* __restrict__ src, const int* __restrict__ dst,
                       const float* __restrict__ w, int e) {
    int i = blockIdx.x * blockDim.x + threadIdx.x;
    if (i < e) {
        int s = src[i], d = dst[i];
        float nm = g_dinv[s] * w[i] * g_dinv[d];
        int p = g_rowptr[d] + atomicAdd(&g_fill[d], 1);
        g_csr[p] = make_int2(s, __float_as_int(nm));
        atomicAdd(&g_c[s], nm);
    }
}

// t = x @ W1
#define BM 64
#define BK 32
__global__ __launch_bounds__(256) void k_gemm(const float* __restrict__ x,
                                              const float* __restrict__ W,
                                              int n) {
    __shared__ float As[BK][BM];
    __shared__ float Bs[BK][FDIM];
    const int br  = blockIdx.x * BM;
    const int tid = threadIdx.x;
    const int ty = tid >> 4;
    const int tx = tid & 15;
    float acc[4][8];
#pragma unroll
    for (int r = 0; r < 4; r++)
#pragma unroll
        for (int c = 0; c < 8; c++) acc[r][c] = 0.f;

    for (int k0 = 0; k0 < FDIM; k0 += BK) {
#pragma unroll
        for (int i = 0; i < 2; i++) {
            int li = tid * 2 + i;
            int r = li >> 3, kq = li & 7;
            int gr = br + r; if (gr >= n) gr = n - 1;
            float4 xv = __ldg((const float4*)(x + (size_t)gr * FDIM + k0) + kq);
            As[kq * 4 + 0][r] = xv.x;
            As[kq * 4 + 1][r] = xv.y;
            As[kq * 4 + 2][r] = xv.z;
            As[kq * 4 + 3][r] = xv.w;
        }
#pragma unroll
        for (int i = 0; i < 4; i++) {
            int li = tid + i * 256;
            int k = li >> 5, cq = li & 31;
            float4 wv = __ldg((const float4*)(W + (size_t)(k0 + k) * FDIM) + cq);
            *(float4*)&Bs[k][cq * 4] = wv;
        }
        __syncthreads();
#pragma unroll 8
        for (int k = 0; k < BK; k++) {
            float4 av  = *(const float4*)&As[k][ty * 4];
            float4 bv0 = *(const float4*)&Bs[k][tx * 8];
            float4 bv1 = *(const float4*)&Bs[k][tx * 8 + 4];
            float a[4] = {av.x, av.y, av.z, av.w};
            float b[8] = {bv0.x, bv0.y, bv0.z, bv0.w, bv1.x, bv1.y, bv1.z, bv1.w};
#pragma unroll
            for (int r = 0; r < 4; r++)
#pragma unroll
                for (int c = 0; c < 8; c++) acc[r][c] = fmaf(a[r], b[c], acc[r][c]);
        }
        __syncthreads();
    }
#pragma unroll
    for (int r = 0; r < 4; r++) {
        int gr = br + ty * 4 + r;
        if (gr < n) {
            *(float4*)(g_t + (size_t)gr * FDIM + tx * 8) =
                make_float4(acc[r][0], acc[r][1], acc[r][2], acc[r][3]);
            *(float4*)(g_t + (size_t)gr * FDIM + tx * 8 + 4) =
                make_float4(acc[r][4], acc[r][5], acc[r][6], acc[r][7]);
        }
    }
}

// fused gather + finalize: per node, register accumulation of incoming msgs,
// then h1 = relu(acc + b1), v += c_i * h1
__global__ __launch_bounds__(256) void k_gather(const float* __restrict__ b1, int n) {
    const int lane = threadIdx.x & 31;
    const int wid  = threadIdx.x >> 5;
    const int gw   = blockIdx.x * 8 + wid;
    const int nw   = gridDim.x * 8;
    float4 bv = __ldg((const float4*)b1 + lane);
    float4 vacc = make_float4(0.f, 0.f, 0.f, 0.f);

    for (int i = gw; i < n; i += nw) {
        int beg = __ldg(g_rowptr + i);
        int cnt = __ldg(g_cnt + i);
        float di = __ldg(g_dinv + i);
        float self = di * di;
        float4 tv = __ldg((const float4*)g_t + ((size_t)i << 5) + lane);
        float4 acc = make_float4(self * tv.x, self * tv.y, self * tv.z, self * tv.w);
        int end = beg + cnt;
        int j = beg;
        for (; j + 4 <= end; j += 4) {
            int2 e0 = __ldg(g_csr + j);
            int2 e1 = __ldg(g_csr + j + 1);
            int2 e2 = __ldg(g_csr + j + 2);
            int2 e3 = __ldg(g_csr + j + 3);
            float4 a0 = __ldg((const float4*)g_t + ((size_t)e0.x << 5) + lane);
            float4 a1 = __ldg((const float4*)g_t + ((size_t)e1.x << 5) + lane);
            float4 a2 = __ldg((const float4*)g_t + ((size_t)e2.x << 5) + lane);
            float4 a3 = __ldg((const float4*)g_t + ((size_t)e3.x << 5) + lane);
            float n0 = __int_as_float(e0.y), n1 = __int_as_float(e1.y);
            float n2 = __int_as_float(e2.y), n3 = __int_as_float(e3.y);
            acc.x = fmaf(n0, a0.x, acc.x); acc.y = fmaf(n0, a0.y, acc.y);
            acc.z = fmaf(n0, a0.z, acc.z); acc.w = fmaf(n0, a0.w, acc.w);
            acc.x = fmaf(n1, a1.x, acc.x); acc.y = fmaf(n1, a1.y, acc.y);
            acc.z = fmaf(n1, a1.z, acc.z); acc.w = fmaf(n1, a1.w, acc.w);
            acc.x = fmaf(n2, a2.x, acc.x); acc.y = fmaf(n2, a2.y, acc.y);
            acc.z = fmaf(n2, a2.z, acc.z); acc.w = fmaf(n2, a2.w, acc.w);
            acc.x = fmaf(n3, a3.x, acc.x); acc.y = fmaf(n3, a3.y, acc.y);
            acc.z = fmaf(n3, a3.z, acc.z); acc.w = fmaf(n3, a3.w, acc.w);
        }
        for (; j < end; j++) {
            int2 e0 = __ldg(g_csr + j);
            float4 a0 = __ldg((const float4*)g_t + ((size_t)e0.x << 5) + lane);
            float n0 = __int_as_float(e0.y);
            acc.x = fmaf(n0, a0.x, acc.x); acc.y = fmaf(n0, a0.y, acc.y);
            acc.z = fmaf(n0, a0.z, acc.z); acc.w = fmaf(n0, a0.w, acc.w);
        }
        float ci = __ldg(g_c + i);
        float4 h;
        h.x = fmaxf(acc.x + bv.x, 0.f);
        h.y = fmaxf(acc.y + bv.y, 0.f);
        h.z = fmaxf(acc.z + bv.z, 0.f);
        h.w = fmaxf(acc.w + bv.w, 0.f);
        vacc.x = fmaf(ci, h.x, vacc.x);
        vacc.y = fmaf(ci, h.y, vacc.y);
        vacc.z = fmaf(ci, h.z, vacc.z);
        vacc.w = fmaf(ci, h.w, vacc.w);
    }

    __shared__ float sv[FDIM];
    if (threadIdx.x < FDIM) sv[threadIdx.x] = 0.f;
    __syncthreads();
    atomicAdd(&sv[lane * 4 + 0], vacc.x);
    atomicAdd(&sv[lane * 4 + 1], vacc.y);
    atomicAdd(&sv[lane * 4 + 2], vacc.z);
    atomicAdd(&sv[lane * 4 + 3], vacc.w);
    __syncthreads();
    if (threadIdx.x < 32) {
        float4 p = *(const float4*)&sv[threadIdx.x * 4];
        red_add_v4(g_v + threadIdx.x * 4, p);
    }
}

// head: g = (1/N) v@W2 + b2;  mu = g@Wmu + bmu;  lv = g@Wlv + blv
__global__ void k_head(const float* __restrict__ W2, const float* __restrict__ b2,
                       const float* __restrict__ Wmu, const float* __restrict__ bmu,
                       const float* __restrict__ Wlv, const float* __restrict__ blv,
                       float* __restrict__ out, float invn) {
    __shared__ float vs[FDIM];
    __shared__ float gs[FDIM];
    int j = threadIdx.x;
    vs[j] = g_v[j];
    __syncthreads();
    float s = 0.f;
#pragma unroll 8
    for (int k = 0; k < FDIM; k++) s = fmaf(vs[k], W2[(size_t)k * FDIM + j], s);
    gs[j] = s * invn + b2[j];
    __syncthreads();
    if (j < LAT) {
        float m = bmu[j];
#pragma unroll 8
        for (int k = 0; k < FDIM; k++) m = fmaf(gs[k], Wmu[(size_t)k * LAT + j], m);
        out[j] = m;
    } else {
        int l = j - LAT;
        float m = blv[l];
#pragma unroll 8
        for (int k = 0; k < FDIM; k++) m = fmaf(gs[k], Wlv[(size_t)k * LAT + l], m);
        out[LAT + l] = m;
    }
}

// ---------------- launch -------------------------------------------------------
extern "C" void kernel_launch(void* const* d_in, const int* in_sizes, int n_in,
                              void* d_out, int out_size) {
    const float* x   = (const float*)d_in[0];
    const int*   ei  = (const int*)d_in[1];
    const float* w   = (const float*)d_in[2];
    const float* W1  = (const float*)d_in[3];
    const float* b1  = (const float*)d_in[4];
    const float* W2  = (const float*)d_in[5];
    const float* b2  = (const float*)d_in[6];
    const float* Wmu = (const float*)d_in[7];
    const float* bmu = (const float*)d_in[8];
    const float* Wlv = (const float*)d_in[9];
    const float* blv = (const float*)d_in[10];
    float* out = (float*)d_out;

    const int n = in_sizes[0] / FDIM;
    const int e = in_sizes[2];
    const int* src = ei;
    const int* dst = ei + e;
    const int nb_scan = (n + SCAN_ELEMS - 1) / SCAN_ELEMS;

    k_init<<<(n + 255) / 256, 256>>>(n);
    k_hist<<<(e + 255) / 256, 256>>>(dst, w, e);
    k_dinv<<<(n + 255) / 256, 256>>>(n);
    k_scan1<<<nb_scan, 256>>>(n);
    k_scan2<<<1, 128>>>(nb_scan);
    k_scan3<<<(n + 255) / 256, 256>>>(n);
    k_fill<<<(e + 255) / 256, 256>>>(src, dst, w, e);
    k_gemm<<<(n + BM - 1) / BM, 256>>>(x, W1, n);
    k_gather<<<1184, 256>>>(b1, n);
    k_head<<<1, FDIM>>>(W2, b2, Wmu, bmu, Wlv, blv, out, 1.0f / (float)n);
}

// round 4
// speedup vs baseline: 1.5681x; 1.1582x over previous
#include <cuda_runtime.h>
#include <cuda_bf16.h>
#include <stdint.h>

#define NNODES 100000
#define NEDGES 1600000
#define FDIM   128
#define LAT    64
#define SCAN_ELEMS 1024
#define NBLK_SCAN ((NNODES + SCAN_ELEMS - 1) / SCAN_ELEMS)   // 98

// ---------------- scratch ----------------------------------------------------
__device__ __nv_bfloat16 g_t[(size_t)NNODES * FDIM];  // t = x @ W1, bf16 (25.6 MB)
__device__ float g_deg[NNODES];
__device__ float g_dinv[NNODES];
__device__ float g_c[NNODES];                   // column sums of Anorm
__device__ int   g_cnt[NNODES];                 // in-degree counts
__device__ int   g_rowptr[NNODES];              // CSR row starts (by dst)
__device__ int   g_fill[NNODES];                // fill cursors
__device__ int   g_bsum[NBLK_SCAN + 32];        // scan partials
__device__ int2  g_csr[NEDGES];                 // packed {src, norm-as-bits}
__device__ float g_v[FDIM];                     // v = sum_i c_i * h1[i]

__device__ __forceinline__ void red_add_v4(float* p, float4 m) {
    asm volatile("red.global.add.v4.f32 [%0], {%1,%2,%3,%4};"
                 :: "l"(p), "f"(m.x), "f"(m.y), "f"(m.z), "f"(m.w) : "memory");
}

__device__ __forceinline__ float4 bf4_to_f4(uint2 u) {
    __nv_bfloat162 p0 = *reinterpret_cast<__nv_bfloat162*>(&u.x);
    __nv_bfloat162 p1 = *reinterpret_cast<__nv_bfloat162*>(&u.y);
    float2 a = __bfloat1622float2(p0);
    float2 b = __bfloat1622float2(p1);
    return make_float4(a.x, a.y, b.x, b.y);
}

__device__ __forceinline__ unsigned pack_bf2(float lo, float hi) {
    __nv_bfloat162 p = __float22bfloat162_rn(make_float2(lo, hi));
    return *reinterpret_cast<unsigned*>(&p);
}

// ---------------- kernels -----------------------------------------------------

__global__ void k_init(int n) {
    int i = blockIdx.x * blockDim.x + threadIdx.x;
    if (i < n) { g_cnt[i] = 0; g_fill[i] = 0; g_deg[i] = 1.0f; }
    if (i < FDIM) g_v[i] = 0.f;
}

// deg[dst] += w ; cnt[dst]++
__global__ void k_hist(const int* __restrict__ dst, const float* __restrict__ w, int e) {
    int i = blockIdx.x * blockDim.x + threadIdx.x;
    if (i < e) {
        int d = dst[i];
        atomicAdd(&g_deg[d], w[i]);
        atomicAdd(&g_cnt[d], 1);
    }
}

// ---- exclusive scan of g_cnt -> g_rowptr ----
__global__ void k_scan1(int n) {
    __shared__ int warp_sums[8];
    int tid = threadIdx.x;                 // 256 threads, 4 elems each
    int idx = blockIdx.x * SCAN_ELEMS + tid * 4;
    int4 v = make_int4(0, 0, 0, 0);
    if (idx + 3 < n) v = *(const int4*)(g_cnt + idx);
    else {
        if (idx + 0 < n) v.x = g_cnt[idx + 0];
        if (idx + 1 < n) v.y = g_cnt[idx + 1];
        if (idx + 2 < n) v.z = g_cnt[idx + 2];
        if (idx + 3 < n) v.w = g_cnt[idx + 3];
    }
    int t = v.x + v.y + v.z + v.w;
    int lane = tid & 31, wid = tid >> 5;
    int s = t;
#pragma unroll
    for (int o = 1; o < 32; o <<= 1) { int u = __shfl_up_sync(~0u, s, o); if (lane >= o) s += u; }
    if (lane == 31) warp_sums[wid] = s;
    __syncthreads();
    if (wid == 0) {
        int ws = (lane < 8) ? warp_sums[lane] : 0;
#pragma unroll
        for (int o = 1; o < 8; o <<= 1) { int u = __shfl_up_sync(~0u, ws, o); if (lane >= o) ws += u; }
        if (lane < 8) warp_sums[lane] = ws;
    }
    __syncthreads();
    int excl = s - t + (wid > 0 ? warp_sums[wid - 1] : 0);
    int o0 = excl, o1 = excl + v.x, o2 = o1 + v.y, o3 = o2 + v.z;
    if (idx + 0 < n) g_rowptr[idx + 0] = o0;
    if (idx + 1 < n) g_rowptr[idx + 1] = o1;
    if (idx + 2 < n) g_rowptr[idx + 2] = o2;
    if (idx + 3 < n) g_rowptr[idx + 3] = o3;
    if (tid == 255) g_bsum[blockIdx.x] = excl + t;
}

__global__ void k_scan2(int nb) {
    int tid = threadIdx.x;                 // 128 threads
    int v = (tid < nb) ? g_bsum[tid] : 0;
    int lane = tid & 31, wid = tid >> 5;
    int s = v;
#pragma unroll
    for (int o = 1; o < 32; o <<= 1) { int u = __shfl_up_sync(~0u, s, o); if (lane >= o) s += u; }
    __shared__ int ws[4];
    if (lane == 31) ws[wid] = s;
    __syncthreads();
    int add = 0;
    for (int k = 0; k < wid; k++) add += ws[k];
    if (tid < nb) g_bsum[tid] = s + add - v;     // exclusive
}

// scan3 fused with dinv/c computation
__global__ void k_scan3(int n) {
    int i = blockIdx.x * blockDim.x + threadIdx.x;
    if (i < n) {
        g_rowptr[i] += g_bsum[i >> 10];
        float di = rsqrtf(g_deg[i]);
        g_dinv[i] = di;
        g_c[i] = di * di;       // self-loop column contribution
    }
}

// CSR fill: place {src, norm} at dst-grouped position; accumulate c[src]
__global__ void k_fill(const int* __restrict__ src, const int* __restrict__ dst,
                       const float* __restrict__ w, int e) {
    int i = blockIdx.x * blockDim.x + threadIdx.x;
    if (i < e) {
        int s = src[i], d = dst[i];
        float nm = g_dinv[s] * w[i] * g_dinv[d];
        int p = g_rowptr[d] + atomicAdd(&g_fill[d], 1);
        g_csr[p] = make_int2(s, __float_as_int(nm));
        atomicAdd(&g_c[s], nm);
    }
}

// t = x @ W1 (output bf16)
#define BM 64
#define BK 32
__global__ __launch_bounds__(256) void k_gemm(const float* __restrict__ x,
                                              const float* __restrict__ W,
                                              int n) {
    __shared__ float As[BK][BM];
    __shared__ float Bs[BK][FDIM];
    const int br  = blockIdx.x * BM;
    const int tid = threadIdx.x;
    const int ty = tid >> 4;
    const int tx = tid & 15;
    float acc[4][8];
#pragma unroll
    for (int r = 0; r < 4; r++)
#pragma unroll
        for (int c = 0; c < 8; c++) acc[r][c] = 0.f;

    for (int k0 = 0; k0 < FDIM; k0 += BK) {
#pragma unroll
        for (int i = 0; i < 2; i++) {
            int li = tid * 2 + i;
            int r = li >> 3, kq = li & 7;
            int gr = br + r; if (gr >= n) gr = n - 1;
            float4 xv = __ldg((const float4*)(x + (size_t)gr * FDIM + k0) + kq);
            As[kq * 4 + 0][r] = xv.x;
            As[kq * 4 + 1][r] = xv.y;
            As[kq * 4 + 2][r] = xv.z;
            As[kq * 4 + 3][r] = xv.w;
        }
#pragma unroll
        for (int i = 0; i < 4; i++) {
            int li = tid + i * 256;
            int k = li >> 5, cq = li & 31;
            float4 wv = __ldg((const float4*)(W + (size_t)(k0 + k) * FDIM) + cq);
            *(float4*)&Bs[k][cq * 4] = wv;
        }
        __syncthreads();
#pragma unroll 8
        for (int k = 0; k < BK; k++) {
            float4 av  = *(const float4*)&As[k][ty * 4];
            float4 bv0 = *(const float4*)&Bs[k][tx * 8];
            float4 bv1 = *(const float4*)&Bs[k][tx * 8 + 4];
            float a[4] = {av.x, av.y, av.z, av.w};
            float b[8] = {bv0.x, bv0.y, bv0.z, bv0.w, bv1.x, bv1.y, bv1.z, bv1.w};
#pragma unroll
            for (int r = 0; r < 4; r++)
#pragma unroll
                for (int c = 0; c < 8; c++) acc[r][c] = fmaf(a[r], b[c], acc[r][c]);
        }
        __syncthreads();
    }
#pragma unroll
    for (int r = 0; r < 4; r++) {
        int gr = br + ty * 4 + r;
        if (gr < n) {
            uint4 o;
            o.x = pack_bf2(acc[r][0], acc[r][1]);
            o.y = pack_bf2(acc[r][2], acc[r][3]);
            o.z = pack_bf2(acc[r][4], acc[r][5]);
            o.w = pack_bf2(acc[r][6], acc[r][7]);
            *(uint4*)(g_t + (size_t)gr * FDIM + tx * 8) = o;
        }
    }
}

// fused gather + finalize: per node, register accumulation of incoming msgs,
// then h1 = relu(acc + b1), v += c_i * h1.  t rows are bf16 (256 B each).
__global__ __launch_bounds__(256) void k_gather(const float* __restrict__ b1, int n) {
    const int lane = threadIdx.x & 31;
    const int wid  = threadIdx.x >> 5;
    const int gw   = blockIdx.x * 8 + wid;
    const int nw   = gridDim.x * 8;
    float4 bv = __ldg((const float4*)b1 + lane);
    float4 vacc = make_float4(0.f, 0.f, 0.f, 0.f);
    const uint2* trows = (const uint2*)g_t;   // 32 uint2 per row

    for (int i = gw; i < n; i += nw) {
        int beg = __ldg(g_rowptr + i);
        int cnt = __ldg(g_cnt + i);
        float di = __ldg(g_dinv + i);
        float self = di * di;
        float4 tv = bf4_to_f4(__ldg(trows + ((size_t)i << 5) + lane));
        float4 acc = make_float4(self * tv.x, self * tv.y, self * tv.z, self * tv.w);
        int end = beg + cnt;
        int j = beg;
        for (; j + 4 <= end; j += 4) {
            int2 e0 = __ldg(g_csr + j);
            int2 e1 = __ldg(g_csr + j + 1);
            int2 e2 = __ldg(g_csr + j + 2);
            int2 e3 = __ldg(g_csr + j + 3);
            float4 a0 = bf4_to_f4(__ldg(trows + ((size_t)e0.x << 5) + lane));
            float4 a1 = bf4_to_f4(__ldg(trows + ((size_t)e1.x << 5) + lane));
            float4 a2 = bf4_to_f4(__ldg(trows + ((size_t)e2.x << 5) + lane));
            float4 a3 = bf4_to_f4(__ldg(trows + ((size_t)e3.x << 5) + lane));
            float n0 = __int_as_float(e0.y), n1 = __int_as_float(e1.y);
            float n2 = __int_as_float(e2.y), n3 = __int_as_float(e3.y);
            acc.x = fmaf(n0, a0.x, acc.x); acc.y = fmaf(n0, a0.y, acc.y);
            acc.z = fmaf(n0, a0.z, acc.z); acc.w = fmaf(n0, a0.w, acc.w);
            acc.x = fmaf(n1, a1.x, acc.x); acc.y = fmaf(n1, a1.y, acc.y);
            acc.z = fmaf(n1, a1.z, acc.z); acc.w = fmaf(n1, a1.w, acc.w);
            acc.x = fmaf(n2, a2.x, acc.x); acc.y = fmaf(n2, a2.y, acc.y);
            acc.z = fmaf(n2, a2.z, acc.z); acc.w = fmaf(n2, a2.w, acc.w);
            acc.x = fmaf(n3, a3.x, acc.x); acc.y = fmaf(n3, a3.y, acc.y);
            acc.z = fmaf(n3, a3.z, acc.z); acc.w = fmaf(n3, a3.w, acc.w);
        }
        for (; j < end; j++) {
            int2 e0 = __ldg(g_csr + j);
            float4 a0 = bf4_to_f4(__ldg(trows + ((size_t)e0.x << 5) + lane));
            float n0 = __int_as_float(e0.y);
            acc.x = fmaf(n0, a0.x, acc.x); acc.y = fmaf(n0, a0.y, acc.y);
            acc.z = fmaf(n0, a0.z, acc.z); acc.w = fmaf(n0, a0.w, acc.w);
        }
        float ci = __ldg(g_c + i);
        float4 h;
        h.x = fmaxf(acc.x + bv.x, 0.f);
        h.y = fmaxf(acc.y + bv.y, 0.f);
        h.z = fmaxf(acc.z + bv.z, 0.f);
        h.w = fmaxf(acc.w + bv.w, 0.f);
        vacc.x = fmaf(ci, h.x, vacc.x);
        vacc.y = fmaf(ci, h.y, vacc.y);
        vacc.z = fmaf(ci, h.z, vacc.z);
        vacc.w = fmaf(ci, h.w, vacc.w);
    }

    __shared__ float sv[FDIM];
    if (threadIdx.x < FDIM) sv[threadIdx.x] = 0.f;
    __syncthreads();
    atomicAdd(&sv[lane * 4 + 0], vacc.x);
    atomicAdd(&sv[lane * 4 + 1], vacc.y);
    atomicAdd(&sv[lane * 4 + 2], vacc.z);
    atomicAdd(&sv[lane * 4 + 3], vacc.w);
    __syncthreads();
    if (threadIdx.x < 32) {
        float4 p = *(const float4*)&sv[threadIdx.x * 4];
        red_add_v4(g_v + threadIdx.x * 4, p);
    }
}

// head: g = (1/N) v@W2 + b2;  mu = g@Wmu + bmu;  lv = g@Wlv + blv
__global__ void k_head(const float* __restrict__ W2, const float* __restrict__ b2,
                       const float* __restrict__ Wmu, const float* __restrict__ bmu,
                       const float* __restrict__ Wlv, const float* __restrict__ blv,
                       float* __restrict__ out, float invn) {
    __shared__ float vs[FDIM];
    __shared__ float gs[FDIM];
    int j = threadIdx.x;
    vs[j] = g_v[j];
    __syncthreads();
    float s = 0.f;
#pragma unroll 8
    for (int k = 0; k < FDIM; k++) s = fmaf(vs[k], W2[(size_t)k * FDIM + j], s);
    gs[j] = s * invn + b2[j];
    __syncthreads();
    if (j < LAT) {
        float m = bmu[j];
#pragma unroll 8
        for (int k = 0; k < FDIM; k++) m = fmaf(gs[k], Wmu[(size_t)k * LAT + j], m);
        out[j] = m;
    } else {
        int l = j - LAT;
        float m = blv[l];
#pragma unroll 8
        for (int k = 0; k < FDIM; k++) m = fmaf(gs[k], Wlv[(size_t)k * LAT + l], m);
        out[LAT + l] = m;
    }
}

// ---------------- launch -------------------------------------------------------
extern "C" void kernel_launch(void* const* d_in, const int* in_sizes, int n_in,
                              void* d_out, int out_size) {
    const float* x   = (const float*)d_in[0];
    const int*   ei  = (const int*)d_in[1];
    const float* w   = (const float*)d_in[2];
    const float* W1  = (const float*)d_in[3];
    const float* b1  = (const float*)d_in[4];
    const float* W2  = (const float*)d_in[5];
    const float* b2  = (const float*)d_in[6];
    const float* Wmu = (const float*)d_in[7];
    const float* bmu = (const float*)d_in[8];
    const float* Wlv = (const float*)d_in[9];
    const float* blv = (const float*)d_in[10];
    float* out = (float*)d_out;

    const int n = in_sizes[0] / FDIM;
    const int e = in_sizes[2];
    const int* src = ei;
    const int* dst = ei + e;
    const int nb_scan = (n + SCAN_ELEMS - 1) / SCAN_ELEMS;

    k_init<<<(n + 255) / 256, 256>>>(n);
    k_hist<<<(e + 255) / 256, 256>>>(dst, w, e);
    k_scan1<<<nb_scan, 256>>>(n);
    k_scan2<<<1, 128>>>(nb_scan);
    k_scan3<<<(n + 255) / 256, 256>>>(n);
    k_fill<<<(e + 255) / 256, 256>>>(src, dst, w, e);
    k_gemm<<<(n + BM - 1) / BM, 256>>>(x, W1, n);
    k_gather<<<1184, 256>>>(b1, n);
    k_head<<<1, FDIM>>>(W2, b2, Wmu, bmu, Wlv, blv, out, 1.0f / (float)n);
}

// round 5
// speedup vs baseline: 1.6389x; 1.0452x over previous
#include <cuda_runtime.h>
#include <cuda_bf16.h>
#include <stdint.h>

#define NNODES 100000
#define NEDGES 1600000
#define FDIM   128
#define LAT    64
#define SCAN_ELEMS 1024
#define NBLK_SCAN ((NNODES + SCAN_ELEMS - 1) / SCAN_ELEMS)   // 98

// ---------------- scratch ----------------------------------------------------
__device__ __nv_bfloat16 g_t[(size_t)NNODES * FDIM];  // t = x @ W1, bf16 (25.6 MB)
__device__ float g_deg[NNODES];
__device__ float g_dinv[NNODES];
__device__ float g_c[NNODES];                   // column sums of Anorm
__device__ int   g_cnt[NNODES];                 // in-degree counts
__device__ int   g_rowptr[NNODES];              // CSR row starts (by dst)
__device__ int   g_fill[NNODES];                // fill cursors
__device__ int   g_bsum[NBLK_SCAN + 32];        // scan partials
__device__ int2  g_csr[NEDGES];                 // packed {src, norm-as-bits}
__device__ float g_v[FDIM];                     // v = sum_i c_i * h1[i]

__device__ __forceinline__ void red_add_v4(float* p, float4 m) {
    asm volatile("red.global.add.v4.f32 [%0], {%1,%2,%3,%4};"
                 :: "l"(p), "f"(m.x), "f"(m.y), "f"(m.z), "f"(m.w) : "memory");
}

__device__ __forceinline__ unsigned pack_bf2(float lo, float hi) {
    __nv_bfloat162 p = __float22bfloat162_rn(make_float2(lo, hi));
    return *reinterpret_cast<unsigned*>(&p);
}

// 8 bf16 (uint4) -> 8 floats
__device__ __forceinline__ void bf8_to_f8(uint4 u, float* f) {
    __nv_bfloat162 p0 = *reinterpret_cast<__nv_bfloat162*>(&u.x);
    __nv_bfloat162 p1 = *reinterpret_cast<__nv_bfloat162*>(&u.y);
    __nv_bfloat162 p2 = *reinterpret_cast<__nv_bfloat162*>(&u.z);
    __nv_bfloat162 p3 = *reinterpret_cast<__nv_bfloat162*>(&u.w);
    float2 a = __bfloat1622float2(p0);
    float2 b = __bfloat1622float2(p1);
    float2 c = __bfloat1622float2(p2);
    float2 d = __bfloat1622float2(p3);
    f[0] = a.x; f[1] = a.y; f[2] = b.x; f[3] = b.y;
    f[4] = c.x; f[5] = c.y; f[6] = d.x; f[7] = d.y;
}

// ---------------- kernels -----------------------------------------------------

__global__ void k_init(int n) {
    int i = blockIdx.x * blockDim.x + threadIdx.x;
    if (i < n) { g_cnt[i] = 0; g_fill[i] = 0; g_deg[i] = 1.0f; }
    if (i < FDIM) g_v[i] = 0.f;
}

__global__ void k_hist(const int* __restrict__ dst, const float* __restrict__ w, int e) {
    int i = blockIdx.x * blockDim.x + threadIdx.x;
    if (i < e) {
        int d = dst[i];
        atomicAdd(&g_deg[d], w[i]);
        atomicAdd(&g_cnt[d], 1);
    }
}

// ---- exclusive scan of g_cnt -> g_rowptr ----
__global__ void k_scan1(int n) {
    __shared__ int warp_sums[8];
    int tid = threadIdx.x;
    int idx = blockIdx.x * SCAN_ELEMS + tid * 4;
    int4 v = make_int4(0, 0, 0, 0);
    if (idx + 3 < n) v = *(const int4*)(g_cnt + idx);
    else {
        if (idx + 0 < n) v.x = g_cnt[idx + 0];
        if (idx + 1 < n) v.y = g_cnt[idx + 1];
        if (idx + 2 < n) v.z = g_cnt[idx + 2];
        if (idx + 3 < n) v.w = g_cnt[idx + 3];
    }
    int t = v.x + v.y + v.z + v.w;
    int lane = tid & 31, wid = tid >> 5;
    int s = t;
#pragma unroll
    for (int o = 1; o < 32; o <<= 1) { int u = __shfl_up_sync(~0u, s, o); if (lane >= o) s += u; }
    if (lane == 31) warp_sums[wid] = s;
    __syncthreads();
    if (wid == 0) {
        int ws = (lane < 8) ? warp_sums[lane] : 0;
#pragma unroll
        for (int o = 1; o < 8; o <<= 1) { int u = __shfl_up_sync(~0u, ws, o); if (lane >= o) ws += u; }
        if (lane < 8) warp_sums[lane] = ws;
    }
    __syncthreads();
    int excl = s - t + (wid > 0 ? warp_sums[wid - 1] : 0);
    int o0 = excl, o1 = excl + v.x, o2 = o1 + v.y, o3 = o2 + v.z;
    if (idx + 0 < n) g_rowptr[idx + 0] = o0;
    if (idx + 1 < n) g_rowptr[idx + 1] = o1;
    if (idx + 2 < n) g_rowptr[idx + 2] = o2;
    if (idx + 3 < n) g_rowptr[idx + 3] = o3;
    if (tid == 255) g_bsum[blockIdx.x] = excl + t;
}

__global__ void k_scan2(int nb) {
    int tid = threadIdx.x;
    int v = (tid < nb) ? g_bsum[tid] : 0;
    int lane = tid & 31, wid = tid >> 5;
    int s = v;
#pragma unroll
    for (int o = 1; o < 32; o <<= 1) { int u = __shfl_up_sync(~0u, s, o); if (lane >= o) s += u; }
    __shared__ int ws[4];
    if (lane == 31) ws[wid] = s;
    __syncthreads();
    int add = 0;
    for (int k = 0; k < wid; k++) add += ws[k];
    if (tid < nb) g_bsum[tid] = s + add - v;
}

// scan3 fused with dinv/c computation
__global__ void k_scan3(int n) {
    int i = blockIdx.x * blockDim.x + threadIdx.x;
    if (i < n) {
        g_rowptr[i] += g_bsum[i >> 10];
        float di = rsqrtf(g_deg[i]);
        g_dinv[i] = di;
        g_c[i] = di * di;
    }
}

// CSR fill
__global__ void k_fill(const int* __restrict__ src, const int* __restrict__ dst,
                       const float* __restrict__ w, int e) {
    int i = blockIdx.x * blockDim.x + threadIdx.x;
    if (i < e) {
        int s = src[i], d = dst[i];
        float nm = g_dinv[s] * w[i] * g_dinv[d];
        int p = g_rowptr[d] + atomicAdd(&g_fill[d], 1);
        g_csr[p] = make_int2(s, __float_as_int(nm));
        atomicAdd(&g_c[s], nm);
    }
}

// t = x @ W1 (output bf16)
#define BM 64
#define BK 32
__global__ __launch_bounds__(256) void k_gemm(const float* __restrict__ x,
                                              const float* __restrict__ W,
                                              int n) {
    __shared__ float As[BK][BM];
    __shared__ float Bs[BK][FDIM];
    const int br  = blockIdx.x * BM;
    const int tid = threadIdx.x;
    const int ty = tid >> 4;
    const int tx = tid & 15;
    float acc[4][8];
#pragma unroll
    for (int r = 0; r < 4; r++)
#pragma unroll
        for (int c = 0; c < 8; c++) acc[r][c] = 0.f;

    for (int k0 = 0; k0 < FDIM; k0 += BK) {
#pragma unroll
        for (int i = 0; i < 2; i++) {
            int li = tid * 2 + i;
            int r = li >> 3, kq = li & 7;
            int gr = br + r; if (gr >= n) gr = n - 1;
            float4 xv = __ldg((const float4*)(x + (size_t)gr * FDIM + k0) + kq);
            As[kq * 4 + 0][r] = xv.x;
            As[kq * 4 + 1][r] = xv.y;
            As[kq * 4 + 2][r] = xv.z;
            As[kq * 4 + 3][r] = xv.w;
        }
#pragma unroll
        for (int i = 0; i < 4; i++) {
            int li = tid + i * 256;
            int k = li >> 5, cq = li & 31;
            float4 wv = __ldg((const float4*)(W + (size_t)(k0 + k) * FDIM) + cq);
            *(float4*)&Bs[k][cq * 4] = wv;
        }
        __syncthreads();
#pragma unroll 8
        for (int k = 0; k < BK; k++) {
            float4 av  = *(const float4*)&As[k][ty * 4];
            float4 bv0 = *(const float4*)&Bs[k][tx * 8];
            float4 bv1 = *(const float4*)&Bs[k][tx * 8 + 4];
            float a[4] = {av.x, av.y, av.z, av.w};
            float b[8] = {bv0.x, bv0.y, bv0.z, bv0.w, bv1.x, bv1.y, bv1.z, bv1.w};
#pragma unroll
            for (int r = 0; r < 4; r++)
#pragma unroll
                for (int c = 0; c < 8; c++) acc[r][c] = fmaf(a[r], b[c], acc[r][c]);
        }
        __syncthreads();
    }
#pragma unroll
    for (int r = 0; r < 4; r++) {
        int gr = br + ty * 4 + r;
        if (gr < n) {
            uint4 o;
            o.x = pack_bf2(acc[r][0], acc[r][1]);
            o.y = pack_bf2(acc[r][2], acc[r][3]);
            o.z = pack_bf2(acc[r][4], acc[r][5]);
            o.w = pack_bf2(acc[r][6], acc[r][7]);
            *(uint4*)(g_t + (size_t)gr * FDIM + tx * 8) = o;
        }
    }
}

// fused gather + finalize. Half-warp per edge: 16 lanes x uint4 (=8 bf16) cover
// a 256B row; the two halves process alternating edges and combine via shfl.
__global__ __launch_bounds__(256) void k_gather(const float* __restrict__ b1, int n) {
    const int lane = threadIdx.x & 31;
    const int half = lane >> 4;          // 0 or 1
    const int hl   = lane & 15;          // position within half-warp
    const int wid  = threadIdx.x >> 5;
    const int gw   = blockIdx.x * 8 + wid;
    const int nw   = gridDim.x * 8;
    const uint4* trows = (const uint4*)g_t;   // 16 uint4 per row

    float b[8];
    {
        float4 b0 = __ldg((const float4*)b1 + hl * 2);
        float4 b1v = __ldg((const float4*)b1 + hl * 2 + 1);
        b[0] = b0.x; b[1] = b0.y; b[2] = b0.z; b[3] = b0.w;
        b[4] = b1v.x; b[5] = b1v.y; b[6] = b1v.z; b[7] = b1v.w;
    }
    float vacc[8];
#pragma unroll
    for (int k = 0; k < 8; k++) vacc[k] = 0.f;

    for (int i = gw; i < n; i += nw) {
        int beg = __ldg(g_rowptr + i);
        int cnt = __ldg(g_cnt + i);
        float acc[8];
        {
            float di = __ldg(g_dinv + i);
            float selfw = half ? 0.f : di * di;
            float f[8];
            bf8_to_f8(__ldg(trows + ((size_t)i << 4) + hl), f);
#pragma unroll
            for (int k = 0; k < 8; k++) acc[k] = selfw * f[k];
        }
        int end = beg + cnt;
        int j = beg + half;
        for (; j + 2 < end; j += 4) {     // 2 edges per half per iter
            int2 e0 = __ldg(g_csr + j);
            int2 e1 = __ldg(g_csr + j + 2);
            float f0[8], f1[8];
            bf8_to_f8(__ldg(trows + ((size_t)e0.x << 4) + hl), f0);
            bf8_to_f8(__ldg(trows + ((size_t)e1.x << 4) + hl), f1);
            float n0 = __int_as_float(e0.y);
            float n1 = __int_as_float(e1.y);
#pragma unroll
            for (int k = 0; k < 8; k++) acc[k] = fmaf(n0, f0[k], acc[k]);
#pragma unroll
            for (int k = 0; k < 8; k++) acc[k] = fmaf(n1, f1[k], acc[k]);
        }
        if (j < end) {
            int2 e0 = __ldg(g_csr + j);
            float f0[8];
            bf8_to_f8(__ldg(trows + ((size_t)e0.x << 4) + hl), f0);
            float n0 = __int_as_float(e0.y);
#pragma unroll
            for (int k = 0; k < 8; k++) acc[k] = fmaf(n0, f0[k], acc[k]);
        }
        // combine the two half-warps
#pragma unroll
        for (int k = 0; k < 8; k++) acc[k] += __shfl_xor_sync(~0u, acc[k], 16);
        if (!half) {
            float ci = __ldg(g_c + i);
#pragma unroll
            for (int k = 0; k < 8; k++) {
                float h = fmaxf(acc[k] + b[k], 0.f);
                vacc[k] = fmaf(ci, h, vacc[k]);
            }
        }
    }

    __shared__ float sv[FDIM];
    if (threadIdx.x < FDIM) sv[threadIdx.x] = 0.f;
    __syncthreads();
    if (!half) {
#pragma unroll
        for (int k = 0; k < 8; k++) atomicAdd(&sv[hl * 8 + k], vacc[k]);
    }
    __syncthreads();
    if (threadIdx.x < 32) {
        float4 p = *(const float4*)&sv[threadIdx.x * 4];
        red_add_v4(g_v + threadIdx.x * 4, p);
    }
}

// head
__global__ void k_head(const float* __restrict__ W2, const float* __restrict__ b2,
                       const float* __restrict__ Wmu, const float* __restrict__ bmu,
                       const float* __restrict__ Wlv, const float* __restrict__ blv,
                       float* __restrict__ out, float invn) {
    __shared__ float vs[FDIM];
    __shared__ float gs[FDIM];
    int j = threadIdx.x;
    vs[j] = g_v[j];
    __syncthreads();
    float s = 0.f;
#pragma unroll 8
    for (int k = 0; k < FDIM; k++) s = fmaf(vs[k], W2[(size_t)k * FDIM + j], s);
    gs[j] = s * invn + b2[j];
    __syncthreads();
    if (j < LAT) {
        float m = bmu[j];
#pragma unroll 8
        for (int k = 0; k < FDIM; k++) m = fmaf(gs[k], Wmu[(size_t)k * LAT + j], m);
        out[j] = m;
    } else {
        int l = j - LAT;
        float m = blv[l];
#pragma unroll 8
        for (int k = 0; k < FDIM; k++) m = fmaf(gs[k], Wlv[(size_t)k * LAT + l], m);
        out[LAT + l] = m;
    }
}

// ---------------- launch -------------------------------------------------------
extern "C" void kernel_launch(void* const* d_in, const int* in_sizes, int n_in,
                              void* d_out, int out_size) {
    const float* x   = (const float*)d_in[0];
    const int*   ei  = (const int*)d_in[1];
    const float* w   = (const float*)d_in[2];
    const float* W1  = (const float*)d_in[3];
    const float* b1  = (const float*)d_in[4];
    const float* W2  = (const float*)d_in[5];
    const float* b2  = (const float*)d_in[6];
    const float* Wmu = (const float*)d_in[7];
    const float* bmu = (const float*)d_in[8];
    const float* Wlv = (const float*)d_in[9];
    const float* blv = (const float*)d_in[10];
    float* out = (float*)d_out;

    const int n = in_sizes[0] / FDIM;
    const int e = in_sizes[2];
    const int* src = ei;
    const int* dst = ei + e;
    const int nb_scan = (n + SCAN_ELEMS - 1) / SCAN_ELEMS;

    // Side stream for the independent GEMM (standard capture fork pattern).
    cudaStream_t s2;
    cudaStreamCreate(&s2);
    cudaEvent_t ev_fork, ev_join;
    cudaEventCreateWithFlags(&ev_fork, cudaEventDisableTiming);
    cudaEventCreateWithFlags(&ev_join, cudaEventDisableTiming);

    cudaEventRecord(ev_fork, 0);
    cudaStreamWaitEvent(s2, ev_fork, 0);
    k_gemm<<<(n + BM - 1) / BM, 256, 0, s2>>>(x, W1, n);
    cudaEventRecord(ev_join, s2);

    // CSR-build chain on the main (captured) stream, concurrent with GEMM.
    k_init<<<(n + 255) / 256, 256>>>(n);
    k_hist<<<(e + 255) / 256, 256>>>(dst, w, e);
    k_scan1<<<nb_scan, 256>>>(n);
    k_scan2<<<1, 128>>>(nb_scan);
    k_scan3<<<(n + 255) / 256, 256>>>(n);
    k_fill<<<(e + 255) / 256, 256>>>(src, dst, w, e);

    cudaStreamWaitEvent(0, ev_join, 0);   // join: gather needs both branches
    k_gather<<<1184, 256>>>(b1, n);
    k_head<<<1, FDIM>>>(W2, b2, Wmu, bmu, Wlv, blv, out, 1.0f / (float)n);
}

// round 6
// speedup vs baseline: 2.2159x; 1.3520x over previous
#include <cuda_runtime.h>
#include <cuda_bf16.h>
#include <stdint.h>

#define NNODES 100000
#define NEDGES 1600000
#define FDIM   128
#define LAT    64
#define SCAN_ELEMS 1024
#define NBLK_SCAN ((NNODES + SCAN_ELEMS - 1) / SCAN_ELEMS)   // 98

// ---------------- scratch ----------------------------------------------------
__device__ __nv_bfloat16 g_t[(size_t)NNODES * FDIM];  // t = x @ W1, bf16 (25.6 MB)
__device__ float g_deg[NNODES];
__device__ float g_dinv[NNODES];
__device__ float g_c[NNODES];                   // column sums of Anorm
__device__ int   g_cnt[NNODES];                 // in-degree counts
__device__ int   g_rowptr[NNODES];              // CSR row starts (by dst)
__device__ int   g_fill[NNODES];                // fill cursors
__device__ int   g_bsum[NBLK_SCAN + 32];        // scan partials
__device__ int2  g_csr[NEDGES];                 // packed {src, norm-as-bits}
__device__ float g_v[FDIM];                     // v = sum_i c_i * h1[i]

__device__ __forceinline__ void red_add_v4(float* p, float4 m) {
    asm volatile("red.global.add.v4.f32 [%0], {%1,%2,%3,%4};"
                 :: "l"(p), "f"(m.x), "f"(m.y), "f"(m.z), "f"(m.w) : "memory");
}

__device__ __forceinline__ unsigned pack_bf2(float lo, float hi) {
    __nv_bfloat162 p = __float22bfloat162_rn(make_float2(lo, hi));
    return *reinterpret_cast<unsigned*>(&p);
}

// 8 bf16 (uint4) -> 8 floats
__device__ __forceinline__ void bf8_to_f8(uint4 u, float* f) {
    __nv_bfloat162 p0 = *reinterpret_cast<__nv_bfloat162*>(&u.x);
    __nv_bfloat162 p1 = *reinterpret_cast<__nv_bfloat162*>(&u.y);
    __nv_bfloat162 p2 = *reinterpret_cast<__nv_bfloat162*>(&u.z);
    __nv_bfloat162 p3 = *reinterpret_cast<__nv_bfloat162*>(&u.w);
    float2 a = __bfloat1622float2(p0);
    float2 b = __bfloat1622float2(p1);
    float2 c = __bfloat1622float2(p2);
    float2 d = __bfloat1622float2(p3);
    f[0] = a.x; f[1] = a.y; f[2] = b.x; f[3] = b.y;
    f[4] = c.x; f[5] = c.y; f[6] = d.x; f[7] = d.y;
}

// ---------------- kernels -----------------------------------------------------

__global__ void k_init(int n) {
    int i = blockIdx.x * blockDim.x + threadIdx.x;
    if (i < n) { g_cnt[i] = 0; g_fill[i] = 0; g_deg[i] = 1.0f; }
    if (i < FDIM) g_v[i] = 0.f;
}

__global__ void k_hist(const int* __restrict__ dst, const float* __restrict__ w, int e) {
    int i = blockIdx.x * blockDim.x + threadIdx.x;
    if (i < e) {
        int d = dst[i];
        atomicAdd(&g_deg[d], w[i]);
        atomicAdd(&g_cnt[d], 1);
    }
}

// ---- exclusive scan of g_cnt -> g_rowptr ----
__global__ void k_scan1(int n) {
    __shared__ int warp_sums[8];
    int tid = threadIdx.x;
    int idx = blockIdx.x * SCAN_ELEMS + tid * 4;
    int4 v = make_int4(0, 0, 0, 0);
    if (idx + 3 < n) v = *(const int4*)(g_cnt + idx);
    else {
        if (idx + 0 < n) v.x = g_cnt[idx + 0];
        if (idx + 1 < n) v.y = g_cnt[idx + 1];
        if (idx + 2 < n) v.z = g_cnt[idx + 2];
        if (idx + 3 < n) v.w = g_cnt[idx + 3];
    }
    int t = v.x + v.y + v.z + v.w;
    int lane = tid & 31, wid = tid >> 5;
    int s = t;
#pragma unroll
    for (int o = 1; o < 32; o <<= 1) { int u = __shfl_up_sync(~0u, s, o); if (lane >= o) s += u; }
    if (lane == 31) warp_sums[wid] = s;
    __syncthreads();
    if (wid == 0) {
        int ws = (lane < 8) ? warp_sums[lane] : 0;
#pragma unroll
        for (int o = 1; o < 8; o <<= 1) { int u = __shfl_up_sync(~0u, ws, o); if (lane >= o) ws += u; }
        if (lane < 8) warp_sums[lane] = ws;
    }
    __syncthreads();
    int excl = s - t + (wid > 0 ? warp_sums[wid - 1] : 0);
    int o0 = excl, o1 = excl + v.x, o2 = o1 + v.y, o3 = o2 + v.z;
    if (idx + 0 < n) g_rowptr[idx + 0] = o0;
    if (idx + 1 < n) g_rowptr[idx + 1] = o1;
    if (idx + 2 < n) g_rowptr[idx + 2] = o2;
    if (idx + 3 < n) g_rowptr[idx + 3] = o3;
    if (tid == 255) g_bsum[blockIdx.x] = excl + t;
}

__global__ void k_scan2(int nb) {
    int tid = threadIdx.x;
    int v = (tid < nb) ? g_bsum[tid] : 0;
    int lane = tid & 31, wid = tid >> 5;
    int s = v;
#pragma unroll
    for (int o = 1; o < 32; o <<= 1) { int u = __shfl_up_sync(~0u, s, o); if (lane >= o) s += u; }
    __shared__ int ws[4];
    if (lane == 31) ws[wid] = s;
    __syncthreads();
    int add = 0;
    for (int k = 0; k < wid; k++) add += ws[k];
    if (tid < nb) g_bsum[tid] = s + add - v;
}

// scan3 fused with dinv/c computation
__global__ void k_scan3(int n) {
    int i = blockIdx.x * blockDim.x + threadIdx.x;
    if (i < n) {
        g_rowptr[i] += g_bsum[i >> 10];
        float di = rsqrtf(g_deg[i]);
        g_dinv[i] = di;
        g_c[i] = di * di;
    }
}

// CSR fill
__global__ void k_fill(const int* __restrict__ src, const int* __restrict__ dst,
                       const float* __restrict__ w, int e) {
    int i = blockIdx.x * blockDim.x + threadIdx.x;
    if (i < e) {
        int s = src[i], d = dst[i];
        float nm = g_dinv[s] * w[i] * g_dinv[d];
        int p = g_rowptr[d] + atomicAdd(&g_fill[d], 1);
        g_csr[p] = make_int2(s, __float_as_int(nm));
        atomicAdd(&g_c[s], nm);
    }
}

// ---------------- tensor-core GEMM: t = bf16(x) @ bf16(W1), fp32 accum -------
// Block: 128 rows x full 128 cols. 8 warps, each warp computes a 16x128 strip
// as 16 m16n8k16 HMMA tiles. x and W staged in smem as bf16, 136-elem row pad
// (68 words -> 4-bank row offset -> conflict-free quad reads).
#define SROW 136
__global__ __launch_bounds__(256) void k_gemm_tc(const float* __restrict__ x,
                                                 const float* __restrict__ W,
                                                 int n) {
    extern __shared__ __nv_bfloat16 smem[];
    __nv_bfloat16 (*sA)[SROW] = (__nv_bfloat16(*)[SROW])smem;                 // [128][136] x rows
    __nv_bfloat16 (*sB)[SROW] = (__nv_bfloat16(*)[SROW])(smem + 128 * SROW);  // [128][136] W^T: [n][k]
    const int tid = threadIdx.x;
    const int br  = blockIdx.x * 128;

    // stage W transposed ([n][k]) as bf16
    for (int idx = tid; idx < FDIM * FDIM; idx += 256) {
        int k = idx >> 7, c = idx & 127;
        sB[c][k] = __float2bfloat16(W[idx]);
    }
    // stage x rows as bf16 (float4 gmem loads)
    for (int idx = tid; idx < 128 * 32; idx += 256) {
        int r = idx >> 5, q = idx & 31;
        int gr = br + r; if (gr >= n) gr = n - 1;
        float4 v = __ldg((const float4*)(x + (size_t)gr * FDIM) + q);
        __nv_bfloat16* p = &sA[r][q * 4];
        p[0] = __float2bfloat16(v.x);
        p[1] = __float2bfloat16(v.y);
        p[2] = __float2bfloat16(v.z);
        p[3] = __float2bfloat16(v.w);
    }
    __syncthreads();

    const int wid  = tid >> 5, lane = tid & 31;
    const int g    = lane >> 2;       // groupID 0..7
    const int tg   = lane & 3;        // thread-in-group
    const int row0 = wid * 16;

    float c[16][4];
#pragma unroll
    for (int t = 0; t < 16; t++)
#pragma unroll
        for (int q = 0; q < 4; q++) c[t][q] = 0.f;

#pragma unroll
    for (int k0 = 0; k0 < FDIM; k0 += 16) {
        unsigned a0 = *(const unsigned*)&sA[row0 + g][k0 + tg * 2];
        unsigned a1 = *(const unsigned*)&sA[row0 + g + 8][k0 + tg * 2];
        unsigned a2 = *(const unsigned*)&sA[row0 + g][k0 + tg * 2 + 8];
        unsigned a3 = *(const unsigned*)&sA[row0 + g + 8][k0 + tg * 2 + 8];
#pragma unroll
        for (int t = 0; t < 16; t++) {
            unsigned b0 = *(const unsigned*)&sB[t * 8 + g][k0 + tg * 2];
            unsigned b1 = *(const unsigned*)&sB[t * 8 + g][k0 + tg * 2 + 8];
            asm volatile(
                "mma.sync.aligned.m16n8k16.row.col.f32.bf16.bf16.f32 "
                "{%0,%1,%2,%3}, {%4,%5,%6,%7}, {%8,%9}, {%0,%1,%2,%3};"
                : "+f"(c[t][0]), "+f"(c[t][1]), "+f"(c[t][2]), "+f"(c[t][3])
                : "r"(a0), "r"(a1), "r"(a2), "r"(a3), "r"(b0), "r"(b1));
        }
    }

    // store: lane owns rows (row0+g, row0+g+8), cols t*8 + tg*2 .. +1
    int r0 = br + row0 + g;
    int r1 = r0 + 8;
#pragma unroll
    for (int t = 0; t < 16; t++) {
        int col = t * 8 + tg * 2;
        if (r0 < n) *(unsigned*)(g_t + (size_t)r0 * FDIM + col) = pack_bf2(c[t][0], c[t][1]);
        if (r1 < n) *(unsigned*)(g_t + (size_t)r1 * FDIM + col) = pack_bf2(c[t][2], c[t][3]);
    }
}

// fused gather + finalize. Half-warp per edge: 16 lanes x uint4 (=8 bf16) cover
// a 256B row; the two halves process alternating edges and combine via shfl.
__global__ __launch_bounds__(256) void k_gather(const float* __restrict__ b1, int n) {
    const int lane = threadIdx.x & 31;
    const int half = lane >> 4;
    const int hl   = lane & 15;
    const int wid  = threadIdx.x >> 5;
    const int gw   = blockIdx.x * 8 + wid;
    const int nw   = gridDim.x * 8;
    const uint4* trows = (const uint4*)g_t;   // 16 uint4 per row

    float b[8];
    {
        float4 b0 = __ldg((const float4*)b1 + hl * 2);
        float4 b1v = __ldg((const float4*)b1 + hl * 2 + 1);
        b[0] = b0.x; b[1] = b0.y; b[2] = b0.z; b[3] = b0.w;
        b[4] = b1v.x; b[5] = b1v.y; b[6] = b1v.z; b[7] = b1v.w;
    }
    float vacc[8];
#pragma unroll
    for (int k = 0; k < 8; k++) vacc[k] = 0.f;

    for (int i = gw; i < n; i += nw) {
        int beg = __ldg(g_rowptr + i);
        int cnt = __ldg(g_cnt + i);
        float acc[8];
        {
            float di = __ldg(g_dinv + i);
            float selfw = half ? 0.f : di * di;
            float f[8];
            bf8_to_f8(__ldg(trows + ((size_t)i << 4) + hl), f);
#pragma unroll
            for (int k = 0; k < 8; k++) acc[k] = selfw * f[k];
        }
        int end = beg + cnt;
        int j = beg + half;
        for (; j + 2 < end; j += 4) {
            int2 e0 = __ldg(g_csr + j);
            int2 e1 = __ldg(g_csr + j + 2);
            float f0[8], f1[8];
            bf8_to_f8(__ldg(trows + ((size_t)e0.x << 4) + hl), f0);
            bf8_to_f8(__ldg(trows + ((size_t)e1.x << 4) + hl), f1);
            float n0 = __int_as_float(e0.y);
            float n1 = __int_as_float(e1.y);
#pragma unroll
            for (int k = 0; k < 8; k++) acc[k] = fmaf(n0, f0[k], acc[k]);
#pragma unroll
            for (int k = 0; k < 8; k++) acc[k] = fmaf(n1, f1[k], acc[k]);
        }
        if (j < end) {
            int2 e0 = __ldg(g_csr + j);
            float f0[8];
            bf8_to_f8(__ldg(trows + ((size_t)e0.x << 4) + hl), f0);
            float n0 = __int_as_float(e0.y);
#pragma unroll
            for (int k = 0; k < 8; k++) acc[k] = fmaf(n0, f0[k], acc[k]);
        }
#pragma unroll
        for (int k = 0; k < 8; k++) acc[k] += __shfl_xor_sync(~0u, acc[k], 16);
        if (!half) {
            float ci = __ldg(g_c + i);
#pragma unroll
            for (int k = 0; k < 8; k++) {
                float h = fmaxf(acc[k] + b[k], 0.f);
                vacc[k] = fmaf(ci, h, vacc[k]);
            }
        }
    }

    __shared__ float sv[FDIM];
    if (threadIdx.x < FDIM) sv[threadIdx.x] = 0.f;
    __syncthreads();
    if (!half) {
#pragma unroll
        for (int k = 0; k < 8; k++) atomicAdd(&sv[hl * 8 + k], vacc[k]);
    }
    __syncthreads();
    if (threadIdx.x < 32) {
        float4 p = *(const float4*)&sv[threadIdx.x * 4];
        red_add_v4(g_v + threadIdx.x * 4, p);
    }
}

// head
__global__ void k_head(const float* __restrict__ W2, const float* __restrict__ b2,
                       const float* __restrict__ Wmu, const float* __restrict__ bmu,
                       const float* __restrict__ Wlv, const float* __restrict__ blv,
                       float* __restrict__ out, float invn) {
    __shared__ float vs[FDIM];
    __shared__ float gs[FDIM];
    int j = threadIdx.x;
    vs[j] = g_v[j];
    __syncthreads();
    float s = 0.f;
#pragma unroll 8
    for (int k = 0; k < FDIM; k++) s = fmaf(vs[k], W2[(size_t)k * FDIM + j], s);
    gs[j] = s * invn + b2[j];
    __syncthreads();
    if (j < LAT) {
        float m = bmu[j];
#pragma unroll 8
        for (int k = 0; k < FDIM; k++) m = fmaf(gs[k], Wmu[(size_t)k * LAT + j], m);
        out[j] = m;
    } else {
        int l = j - LAT;
        float m = blv[l];
#pragma unroll 8
        for (int k = 0; k < FDIM; k++) m = fmaf(gs[k], Wlv[(size_t)k * LAT + l], m);
        out[LAT + l] = m;
    }
}

// ---------------- launch -------------------------------------------------------
extern "C" void kernel_launch(void* const* d_in, const int* in_sizes, int n_in,
                              void* d_out, int out_size) {
    const float* x   = (const float*)d_in[0];
    const int*   ei  = (const int*)d_in[1];
    const float* w   = (const float*)d_in[2];
    const float* W1  = (const float*)d_in[3];
    const float* b1  = (const float*)d_in[4];
    const float* W2  = (const float*)d_in[5];
    const float* b2  = (const float*)d_in[6];
    const float* Wmu = (const float*)d_in[7];
    const float* bmu = (const float*)d_in[8];
    const float* Wlv = (const float*)d_in[9];
    const float* blv = (const float*)d_in[10];
    float* out = (float*)d_out;

    const int n = in_sizes[0] / FDIM;
    const int e = in_sizes[2];
    const int* src = ei;
    const int* dst = ei + e;
    const int nb_scan = (n + SCAN_ELEMS - 1) / SCAN_ELEMS;
    const int smem_gemm = 2 * 128 * SROW * (int)sizeof(__nv_bfloat16);  // 69,632 B

    static int s_attr_done = 0;
    if (!s_attr_done) {
        cudaFuncSetAttribute(k_gemm_tc, cudaFuncAttributeMaxDynamicSharedMemorySize, smem_gemm);
        s_attr_done = 1;
    }

    // Side stream for the independent GEMM (capture fork pattern).
    cudaStream_t s2;
    cudaStreamCreate(&s2);
    cudaEvent_t ev_fork, ev_join;
    cudaEventCreateWithFlags(&ev_fork, cudaEventDisableTiming);
    cudaEventCreateWithFlags(&ev_join, cudaEventDisableTiming);

    cudaEventRecord(ev_fork, 0);
    cudaStreamWaitEvent(s2, ev_fork, 0);
    k_gemm_tc<<<(n + 127) / 128, 256, smem_gemm, s2>>>(x, W1, n);
    cudaEventRecord(ev_join, s2);

    // CSR-build chain on the main (captured) stream, concurrent with GEMM.
    k_init<<<(n + 255) / 256, 256>>>(n);
    k_hist<<<(e + 255) / 256, 256>>>(dst, w, e);
    k_scan1<<<nb_scan, 256>>>(n);
    k_scan2<<<1, 128>>>(nb_scan);
    k_scan3<<<(n + 255) / 256, 256>>>(n);
    k_fill<<<(e + 255) / 256, 256>>>(src, dst, w, e);

    cudaStreamWaitEvent(0, ev_join, 0);
    k_gather<<<1184, 256>>>(b1, n);
    k_head<<<1, FDIM>>>(W2, b2, Wmu, bmu, Wlv, blv, out, 1.0f / (float)n);
}

// round 7
// speedup vs baseline: 2.3907x; 1.0789x over previous
#include <cuda_runtime.h>
#include <cuda_bf16.h>
#include <stdint.h>

#define NNODES 100000
#define NEDGES 1600000
#define FDIM   128
#define LAT    64
#define SCAN_ELEMS 1024
#define NBLK_SCAN ((NNODES + SCAN_ELEMS - 1) / SCAN_ELEMS)   // 98

// ---------------- scratch ----------------------------------------------------
__device__ __nv_bfloat16 g_t[(size_t)NNODES * FDIM];  // t = x @ W1, bf16 (25.6 MB)
__device__ unsigned long long g_pack[NNODES];   // [63:40] cnt, [39:0] sum(w) Q24
__device__ float g_dinv[NNODES];
__device__ float g_c[NNODES];                   // column sums of Anorm
__device__ int   g_cnt[NNODES];                 // in-degree counts
__device__ int   g_rowptr[NNODES];              // CSR cursor (post-fill = row end)
__device__ int   g_bsum[NBLK_SCAN + 32];        // scan partials
__device__ int2  g_csr[NEDGES];                 // packed {src, norm-as-bits}
__device__ float g_v[FDIM];                     // v = sum_i c_i * h1[i]

__device__ __forceinline__ void red_add_v4(float* p, float4 m) {
    asm volatile("red.global.add.v4.f32 [%0], {%1,%2,%3,%4};"
                 :: "l"(p), "f"(m.x), "f"(m.y), "f"(m.z), "f"(m.w) : "memory");
}

__device__ __forceinline__ unsigned pack_bf2(float lo, float hi) {
    __nv_bfloat162 p = __float22bfloat162_rn(make_float2(lo, hi));
    return *reinterpret_cast<unsigned*>(&p);
}

// 8 bf16 (uint4) -> 8 floats
__device__ __forceinline__ void bf8_to_f8(uint4 u, float* f) {
    __nv_bfloat162 p0 = *reinterpret_cast<__nv_bfloat162*>(&u.x);
    __nv_bfloat162 p1 = *reinterpret_cast<__nv_bfloat162*>(&u.y);
    __nv_bfloat162 p2 = *reinterpret_cast<__nv_bfloat162*>(&u.z);
    __nv_bfloat162 p3 = *reinterpret_cast<__nv_bfloat162*>(&u.w);
    float2 a = __bfloat1622float2(p0);
    float2 b = __bfloat1622float2(p1);
    float2 c = __bfloat1622float2(p2);
    float2 d = __bfloat1622float2(p3);
    f[0] = a.x; f[1] = a.y; f[2] = b.x; f[3] = b.y;
    f[4] = c.x; f[5] = c.y; f[6] = d.x; f[7] = d.y;
}

// ---------------- kernels -----------------------------------------------------

__global__ void k_init(int n) {
    int i = blockIdx.x * blockDim.x + threadIdx.x;
    if (i < n) g_pack[i] = 0ull;
    if (i < FDIM) g_v[i] = 0.f;
}

// one packed 64-bit atomic per edge: cnt++ (Q40 field) and deg += w (Q24 fixed)
__global__ void k_hist(const int* __restrict__ dst, const float* __restrict__ w, int e) {
    int i = blockIdx.x * blockDim.x + threadIdx.x;
    if (i < e) {
        unsigned long long pk = (1ull << 40)
            | (unsigned long long)(unsigned)(w[i] * 16777216.0f);
        atomicAdd(&g_pack[dst[i]], pk);
    }
}

// decode pack -> cnt/dinv/c, then block-local exclusive scan of cnt -> rowptr
__global__ void k_scan1(int n) {
    __shared__ int warp_sums[8];
    int tid = threadIdx.x;
    int idx = blockIdx.x * SCAN_ELEMS + tid * 4;
    int4 v = make_int4(0, 0, 0, 0);
#pragma unroll
    for (int k = 0; k < 4; k++) {
        int i = idx + k;
        if (i < n) {
            unsigned long long pk = g_pack[i];
            int cnt = (int)(pk >> 40);
            float degw = 1.0f + (float)(pk & 0xFFFFFFFFFFull) * (1.0f / 16777216.0f);
            float di = rsqrtf(degw);
            g_dinv[i] = di;
            g_c[i] = di * di;
            g_cnt[i] = cnt;
            ((int*)&v)[k] = cnt;
        }
    }
    int t = v.x + v.y + v.z + v.w;
    int lane = tid & 31, wid = tid >> 5;
    int s = t;
#pragma unroll
    for (int o = 1; o < 32; o <<= 1) { int u = __shfl_up_sync(~0u, s, o); if (lane >= o) s += u; }
    if (lane == 31) warp_sums[wid] = s;
    __syncthreads();
    if (wid == 0) {
        int ws = (lane < 8) ? warp_sums[lane] : 0;
#pragma unroll
        for (int o = 1; o < 8; o <<= 1) { int u = __shfl_up_sync(~0u, ws, o); if (lane >= o) ws += u; }
        if (lane < 8) warp_sums[lane] = ws;
    }
    __syncthreads();
    int excl = s - t + (wid > 0 ? warp_sums[wid - 1] : 0);
    int o0 = excl, o1 = excl + v.x, o2 = o1 + v.y, o3 = o2 + v.z;
    if (idx + 0 < n) g_rowptr[idx + 0] = o0;
    if (idx + 1 < n) g_rowptr[idx + 1] = o1;
    if (idx + 2 < n) g_rowptr[idx + 2] = o2;
    if (idx + 3 < n) g_rowptr[idx + 3] = o3;
    if (tid == 255) g_bsum[blockIdx.x] = excl + t;
}

__global__ void k_scan2(int nb) {
    int tid = threadIdx.x;
    int v = (tid < nb) ? g_bsum[tid] : 0;
    int lane = tid & 31, wid = tid >> 5;
    int s = v;
#pragma unroll
    for (int o = 1; o < 32; o <<= 1) { int u = __shfl_up_sync(~0u, s, o); if (lane >= o) s += u; }
    __shared__ int ws[4];
    if (lane == 31) ws[wid] = s;
    __syncthreads();
    int add = 0;
    for (int k = 0; k < wid; k++) add += ws[k];
    if (tid < nb) g_bsum[tid] = s + add - v;
}

__global__ void k_scan3(int n) {
    int i = blockIdx.x * blockDim.x + threadIdx.x;
    if (i < n) g_rowptr[i] += g_bsum[i >> 10];
}

// CSR fill: rowptr doubles as the cursor (post-fill it equals the row END)
__global__ void k_fill(const int* __restrict__ src, const int* __restrict__ dst,
                       const float* __restrict__ w, int e) {
    int i = blockIdx.x * blockDim.x + threadIdx.x;
    if (i < e) {
        int s = src[i], d = dst[i];
        float nm = g_dinv[s] * w[i] * g_dinv[d];
        int p = atomicAdd(&g_rowptr[d], 1);
        g_csr[p] = make_int2(s, __float_as_int(nm));
        atomicAdd(&g_c[s], nm);
    }
}

// ---------------- tensor-core GEMM: t = bf16(x) @ bf16(W1), fp32 accum -------
#define SROW 136
__global__ __launch_bounds__(256) void k_gemm_tc(const float* __restrict__ x,
                                                 const float* __restrict__ W,
                                                 int n) {
    extern __shared__ __nv_bfloat16 smem[];
    __nv_bfloat16 (*sA)[SROW] = (__nv_bfloat16(*)[SROW])smem;                 // x rows
    __nv_bfloat16 (*sB)[SROW] = (__nv_bfloat16(*)[SROW])(smem + 128 * SROW);  // W^T
    const int tid = threadIdx.x;
    const int br  = blockIdx.x * 128;

    for (int idx = tid; idx < FDIM * FDIM; idx += 256) {
        int k = idx >> 7, c = idx & 127;
        sB[c][k] = __float2bfloat16(W[idx]);
    }
    for (int idx = tid; idx < 128 * 32; idx += 256) {
        int r = idx >> 5, q = idx & 31;
        int gr = br + r; if (gr >= n) gr = n - 1;
        float4 v = __ldg((const float4*)(x + (size_t)gr * FDIM) + q);
        __nv_bfloat16* p = &sA[r][q * 4];
        p[0] = __float2bfloat16(v.x);
        p[1] = __float2bfloat16(v.y);
        p[2] = __float2bfloat16(v.z);
        p[3] = __float2bfloat16(v.w);
    }
    __syncthreads();

    const int wid  = tid >> 5, lane = tid & 31;
    const int g    = lane >> 2;
    const int tg   = lane & 3;
    const int row0 = wid * 16;

    float c[16][4];
#pragma unroll
    for (int t = 0; t < 16; t++)
#pragma unroll
        for (int q = 0; q < 4; q++) c[t][q] = 0.f;

#pragma unroll
    for (int k0 = 0; k0 < FDIM; k0 += 16) {
        unsigned a0 = *(const unsigned*)&sA[row0 + g][k0 + tg * 2];
        unsigned a1 = *(const unsigned*)&sA[row0 + g + 8][k0 + tg * 2];
        unsigned a2 = *(const unsigned*)&sA[row0 + g][k0 + tg * 2 + 8];
        unsigned a3 = *(const unsigned*)&sA[row0 + g + 8][k0 + tg * 2 + 8];
#pragma unroll
        for (int t = 0; t < 16; t++) {
            unsigned b0 = *(const unsigned*)&sB[t * 8 + g][k0 + tg * 2];
            unsigned b1 = *(const unsigned*)&sB[t * 8 + g][k0 + tg * 2 + 8];
            asm volatile(
                "mma.sync.aligned.m16n8k16.row.col.f32.bf16.bf16.f32 "
                "{%0,%1,%2,%3}, {%4,%5,%6,%7}, {%8,%9}, {%0,%1,%2,%3};"
                : "+f"(c[t][0]), "+f"(c[t][1]), "+f"(c[t][2]), "+f"(c[t][3])
                : "r"(a0), "r"(a1), "r"(a2), "r"(a3), "r"(b0), "r"(b1));
        }
    }

    int r0 = br + row0 + g;
    int r1 = r0 + 8;
#pragma unroll
    for (int t = 0; t < 16; t++) {
        int col = t * 8 + tg * 2;
        if (r0 < n) *(unsigned*)(g_t + (size_t)r0 * FDIM + col) = pack_bf2(c[t][0], c[t][1]);
        if (r1 < n) *(unsigned*)(g_t + (size_t)r1 * FDIM + col) = pack_bf2(c[t][2], c[t][3]);
    }
}

// fused gather + finalize. Half-warp per edge (16 lanes x 16B = 256B row),
// 4 edges per half-warp per iteration for MLP.
__global__ __launch_bounds__(256) void k_gather(const float* __restrict__ b1, int n) {
    const int lane = threadIdx.x & 31;
    const int half = lane >> 4;
    const int hl   = lane & 15;
    const int wid  = threadIdx.x >> 5;
    const int gw   = blockIdx.x * 8 + wid;
    const int nw   = gridDim.x * 8;
    const uint4* trows = (const uint4*)g_t;   // 16 uint4 per row

    float b[8];
    {
        float4 b0 = __ldg((const float4*)b1 + hl * 2);
        float4 b1v = __ldg((const float4*)b1 + hl * 2 + 1);
        b[0] = b0.x; b[1] = b0.y; b[2] = b0.z; b[3] = b0.w;
        b[4] = b1v.x; b[5] = b1v.y; b[6] = b1v.z; b[7] = b1v.w;
    }
    float vacc[8];
#pragma unroll
    for (int k = 0; k < 8; k++) vacc[k] = 0.f;

    for (int i = gw; i < n; i += nw) {
        int end = __ldg(g_rowptr + i);        // post-fill cursor == row end
        int cnt = __ldg(g_cnt + i);
        int beg = end - cnt;
        float acc[8];
        {
            float di = __ldg(g_dinv + i);
            float selfw = half ? 0.f : di * di;
            float f[8];
            bf8_to_f8(__ldg(trows + ((size_t)i << 4) + hl), f);
#pragma unroll
            for (int k = 0; k < 8; k++) acc[k] = selfw * f[k];
        }
        int j = beg + half;
        for (; j + 6 < end; j += 8) {         // 4 edges per half per iter
            int2 e0 = __ldg(g_csr + j);
            int2 e1 = __ldg(g_csr + j + 2);
            int2 e2 = __ldg(g_csr + j + 4);
            int2 e3 = __ldg(g_csr + j + 6);
            float f0[8], f1[8], f2[8], f3[8];
            bf8_to_f8(__ldg(trows + ((size_t)e0.x << 4) + hl), f0);
            bf8_to_f8(__ldg(trows + ((size_t)e1.x << 4) + hl), f1);
            bf8_to_f8(__ldg(trows + ((size_t)e2.x << 4) + hl), f2);
            bf8_to_f8(__ldg(trows + ((size_t)e3.x << 4) + hl), f3);
            float n0 = __int_as_float(e0.y);
            float n1 = __int_as_float(e1.y);
            float n2 = __int_as_float(e2.y);
            float n3 = __int_as_float(e3.y);
#pragma unroll
            for (int k = 0; k < 8; k++) acc[k] = fmaf(n0, f0[k], acc[k]);
#pragma unroll
            for (int k = 0; k < 8; k++) acc[k] = fmaf(n1, f1[k], acc[k]);
#pragma unroll
            for (int k = 0; k < 8; k++) acc[k] = fmaf(n2, f2[k], acc[k]);
#pragma unroll
            for (int k = 0; k < 8; k++) acc[k] = fmaf(n3, f3[k], acc[k]);
        }
        for (; j < end; j += 2) {
            int2 e0 = __ldg(g_csr + j);
            float f0[8];
            bf8_to_f8(__ldg(trows + ((size_t)e0.x << 4) + hl), f0);
            float n0 = __int_as_float(e0.y);
#pragma unroll
            for (int k = 0; k < 8; k++) acc[k] = fmaf(n0, f0[k], acc[k]);
        }
#pragma unroll
        for (int k = 0; k < 8; k++) acc[k] += __shfl_xor_sync(~0u, acc[k], 16);
        if (!half) {
            float ci = __ldg(g_c + i);
#pragma unroll
            for (int k = 0; k < 8; k++) {
                float h = fmaxf(acc[k] + b[k], 0.f);
                vacc[k] = fmaf(ci, h, vacc[k]);
            }
        }
    }

    __shared__ float sv[FDIM];
    if (threadIdx.x < FDIM) sv[threadIdx.x] = 0.f;
    __syncthreads();
    if (!half) {
#pragma unroll
        for (int k = 0; k < 8; k++) atomicAdd(&sv[hl * 8 + k], vacc[k]);
    }
    __syncthreads();
    if (threadIdx.x < 32) {
        float4 p = *(const float4*)&sv[threadIdx.x * 4];
        red_add_v4(g_v + threadIdx.x * 4, p);
    }
}

// head
__global__ void k_head(const float* __restrict__ W2, const float* __restrict__ b2,
                       const float* __restrict__ Wmu, const float* __restrict__ bmu,
                       const float* __restrict__ Wlv, const float* __restrict__ blv,
                       float* __restrict__ out, float invn) {
    __shared__ float vs[FDIM];
    __shared__ float gs[FDIM];
    int j = threadIdx.x;
    vs[j] = g_v[j];
    __syncthreads();
    float s = 0.f;
#pragma unroll 8
    for (int k = 0; k < FDIM; k++) s = fmaf(vs[k], W2[(size_t)k * FDIM + j], s);
    gs[j] = s * invn + b2[j];
    __syncthreads();
    if (j < LAT) {
        float m = bmu[j];
#pragma unroll 8
        for (int k = 0; k < FDIM; k++) m = fmaf(gs[k], Wmu[(size_t)k * LAT + j], m);
        out[j] = m;
    } else {
        int l = j - LAT;
        float m = blv[l];
#pragma unroll 8
        for (int k = 0; k < FDIM; k++) m = fmaf(gs[k], Wlv[(size_t)k * LAT + l], m);
        out[LAT + l] = m;
    }
}

// ---------------- launch -------------------------------------------------------
extern "C" void kernel_launch(void* const* d_in, const int* in_sizes, int n_in,
                              void* d_out, int out_size) {
    const float* x   = (const float*)d_in[0];
    const int*   ei  = (const int*)d_in[1];
    const float* w   = (const float*)d_in[2];
    const float* W1  = (const float*)d_in[3];
    const float* b1  = (const float*)d_in[4];
    const float* W2  = (const float*)d_in[5];
    const float* b2  = (const float*)d_in[6];
    const float* Wmu = (const float*)d_in[7];
    const float* bmu = (const float*)d_in[8];
    const float* Wlv = (const float*)d_in[9];
    const float* blv = (const float*)d_in[10];
    float* out = (float*)d_out;

    const int n = in_sizes[0] / FDIM;
    const int e = in_sizes[2];
    const int* src = ei;
    const int* dst = ei + e;
    const int nb_scan = (n + SCAN_ELEMS - 1) / SCAN_ELEMS;
    const int smem_gemm = 2 * 128 * SROW * (int)sizeof(__nv_bfloat16);  // 69,632 B

    static int s_attr_done = 0;
    if (!s_attr_done) {
        cudaFuncSetAttribute(k_gemm_tc, cudaFuncAttributeMaxDynamicSharedMemorySize, smem_gemm);
        s_attr_done = 1;
    }

    // Side stream for the independent GEMM (capture fork pattern).
    cudaStream_t s2;
    cudaStreamCreate(&s2);
    cudaEvent_t ev_fork, ev_join;
    cudaEventCreateWithFlags(&ev_fork, cudaEventDisableTiming);
    cudaEventCreateWithFlags(&ev_join, cudaEventDisableTiming);

    cudaEventRecord(ev_fork, 0);
    cudaStreamWaitEvent(s2, ev_fork, 0);
    k_gemm_tc<<<(n + 127) / 128, 256, smem_gemm, s2>>>(x, W1, n);
    cudaEventRecord(ev_join, s2);

    // CSR-build chain on the main (captured) stream, concurrent with GEMM.
    k_init<<<(n + 255) / 256, 256>>>(n);
    k_hist<<<(e + 255) / 256, 256>>>(dst, w, e);
    k_scan1<<<nb_scan, 256>>>(n);
    k_scan2<<<1, 128>>>(nb_scan);
    k_scan3<<<(n + 255) / 256, 256>>>(n);
    k_fill<<<(e + 255) / 256, 256>>>(src, dst, w, e);

    cudaStreamWaitEvent(0, ev_join, 0);
    k_gather<<<1184, 256>>>(b1, n);
    k_head<<<1, FDIM>>>(W2, b2, Wmu, bmu, Wlv, blv, out, 1.0f / (float)n);
}